// round 4
// baseline (speedup 1.0000x reference)
#include <cuda_runtime.h>

#define NUM_SEG 512
#define D 64
#define D4 (D / 4)     // 16 float4 chunks per row
#define QPS 4          // quarter-blocks per segment in stats

// Scratch (device globals; fully overwritten every call -> deterministic, graph-safe).
__device__ float4 g_psum[NUM_SEG * QPS * D4];
__device__ float  g_psq [NUM_SEG * QPS];
__device__ float4 g_mean[NUM_SEG * D4];
__device__ float  g_inv [NUM_SEG];

__device__ __forceinline__ int lower_bound_i32(const int* __restrict__ a, int n, int v) {
    int lo = 0, hi = n;
    while (lo < hi) {
        int mid = (lo + hi) >> 1;
        if (a[mid] < v) lo = mid + 1; else hi = mid;
    }
    return lo;
}

// K1: partial stats. Block = (segment s, quarter q). 2048 blocks x 256 threads.
__global__ __launch_bounds__(256) void k_stats(
    const float4* __restrict__ x4,   // [N,16] float4 view
    const int* __restrict__ batch,   // [N] sorted int32
    int N)
{
    const int bid = blockIdx.x;
    const int s   = bid >> 2;
    const int q   = bid & 3;
    const int tid = threadIdx.x;

    __shared__ int sh_lo, sh_hi;
    if (tid == 0)  sh_lo = lower_bound_i32(batch, N, s);
    if (tid == 32) sh_hi = lower_bound_i32(batch, N, s + 1);
    __syncthreads();
    const int lo = sh_lo, hi = sh_hi;
    const int len = hi - lo;
    const int qlo = lo + ((len * q) >> 2);
    const int qhi = lo + ((len * (q + 1)) >> 2);

    const int c4 = tid & (D4 - 1);  // column chunk 0..15
    const int rg = tid >> 4;        // row group 0..15

    float4 sum4 = make_float4(0.f, 0.f, 0.f, 0.f);
    float  sq   = 0.f;
    int r = qlo + rg;
    for (; r + 16 < qhi; r += 32) {
        float4 v0 = x4[(size_t)r * D4 + c4];
        float4 v1 = x4[(size_t)(r + 16) * D4 + c4];
        sum4.x += v0.x + v1.x; sum4.y += v0.y + v1.y;
        sum4.z += v0.z + v1.z; sum4.w += v0.w + v1.w;
        sq += v0.x * v0.x + v0.y * v0.y + v0.z * v0.z + v0.w * v0.w;
        sq += v1.x * v1.x + v1.y * v1.y + v1.z * v1.z + v1.w * v1.w;
    }
    if (r < qhi) {
        float4 v0 = x4[(size_t)r * D4 + c4];
        sum4.x += v0.x; sum4.y += v0.y; sum4.z += v0.z; sum4.w += v0.w;
        sq += v0.x * v0.x + v0.y * v0.y + v0.z * v0.z + v0.w * v0.w;
    }

    __shared__ float4 ssum[256];
    __shared__ float  ssq[256];
    ssum[tid] = sum4;
    ssq[tid]  = sq;
    __syncthreads();
    for (int off = 128; off >= D4; off >>= 1) {
        if (tid < off) {
            float4 a = ssum[tid], b = ssum[tid + off];
            a.x += b.x; a.y += b.y; a.z += b.z; a.w += b.w;
            ssum[tid] = a;
            ssq[tid] += ssq[tid + off];
        }
        __syncthreads();
    }
    if (tid < D4) g_psum[bid * D4 + tid] = ssum[tid];
    if (tid == 0) {
        float t = 0.f;
#pragma unroll
        for (int i = 0; i < D4; i++) t += ssq[i];
        g_psq[bid] = t;
    }
}

// K2: finalize. Block = segment, 32 threads.
__global__ __launch_bounds__(32) void k_finalize(
    const int* __restrict__ batch, int N)
{
    const int s = blockIdx.x;
    const int t = threadIdx.x;

    const int lo = lower_bound_i32(batch, N, s);
    const int hi = lower_bound_i32(batch, N, s + 1);
    const float invc = 1.f / (float)max(hi - lo, 1);

    float msq = 0.f;
    if (t < D4) {
        float4 a = g_psum[(s * QPS + 0) * D4 + t];
        float4 b = g_psum[(s * QPS + 1) * D4 + t];
        float4 c = g_psum[(s * QPS + 2) * D4 + t];
        float4 d = g_psum[(s * QPS + 3) * D4 + t];
        float4 m;
        m.x = (a.x + b.x + c.x + d.x) * invc;
        m.y = (a.y + b.y + c.y + d.y) * invc;
        m.z = (a.z + b.z + c.z + d.z) * invc;
        m.w = (a.w + b.w + c.w + d.w) * invc;
        g_mean[s * D4 + t] = m;
        msq = m.x * m.x + m.y * m.y + m.z * m.z + m.w * m.w;
    }
#pragma unroll
    for (int off = 8; off >= 1; off >>= 1)
        msq += __shfl_down_sync(0xffffffffu, msq, off);
    if (t == 0) {
        float sq_tot = g_psq[s * QPS + 0] + g_psq[s * QPS + 1]
                     + g_psq[s * QPS + 2] + g_psq[s * QPS + 3];
        // segment_mean(|x-m|^2) = segment_mean(|x|^2) - |m|^2
        float var = sq_tot * invc - msq;
        g_inv[s] = rsqrtf(var);
    }
}

// K3: apply, reversed traversal (touch the L2-warm tail of x first), two
// descending streams per thread for MLP, streaming loads/stores.
__global__ __launch_bounds__(256) void k_apply(
    const float4* __restrict__ x4,
    const int* __restrict__ batch,
    float4* __restrict__ out4,
    int total4, int half4)
{
    const int j = blockIdx.x * blockDim.x + threadIdx.x;
    if (j >= half4) return;
    const int i0 = total4 - 1 - j;   // stream 1: end -> mid (L2-warm first)
    const int i1 = i0 - half4;       // stream 2: mid -> 0

    const int row0 = i0 >> 4, c0 = i0 & (D4 - 1);
    const int row1 = i1 >> 4, c1 = i1 & (D4 - 1);

    int s0 = batch[row0]; s0 = min(max(s0, 0), NUM_SEG - 1);
    int s1 = batch[row1]; s1 = min(max(s1, 0), NUM_SEG - 1);

    float4 v0 = __ldcs(&x4[i0]);
    float4 v1 = __ldcs(&x4[i1]);

    const float4 m0 = g_mean[s0 * D4 + c0];
    const float4 m1 = g_mean[s1 * D4 + c1];
    const float  g0 = g_inv[s0];
    const float  g1 = g_inv[s1];

    float4 o0, o1;
    o0.x = (v0.x - m0.x) * g0; o0.y = (v0.y - m0.y) * g0;
    o0.z = (v0.z - m0.z) * g0; o0.w = (v0.w - m0.w) * g0;
    o1.x = (v1.x - m1.x) * g1; o1.y = (v1.y - m1.y) * g1;
    o1.z = (v1.z - m1.z) * g1; o1.w = (v1.w - m1.w) * g1;

    __stcs(&out4[i0], o0);
    __stcs(&out4[i1], o1);
}

extern "C" void kernel_launch(void* const* d_in, const int* in_sizes, int n_in,
                              void* d_out, int out_size)
{
    const float* x     = (const float*)d_in[0];   // [N, 64]
    const int*   batch = (const int*)d_in[1];     // [N], sorted int32
    float*       out   = (float*)d_out;

    const int N = in_sizes[1];
    const float4* x4   = (const float4*)x;
    float4*       out4 = (float4*)out;

    k_stats<<<NUM_SEG * QPS, 256>>>(x4, batch, N);
    k_finalize<<<NUM_SEG, 32>>>(batch, N);

    const int total4 = N * D4;
    const int half4  = (total4 + 1) / 2;
    const int blocks = (half4 + 255) / 256;
    k_apply<<<blocks, 256>>>(x4, batch, out4, total4, half4);
}